// round 5
// baseline (speedup 1.0000x reference)
#include <cuda_runtime.h>
#include <math.h>

#define CH   512
#define CS   64
#define CFU  576          // fused channels
#define HW   4096         // 64*64
#define WID  64
#define HQ   62           // 64 - 3 + 1
#define NK   3844         // 62*62

// ---------------- scratch (static device memory; allowed) ----------------
__device__ float g_A[CFU * HW];              // cF_fused  [c][pix]   9.4 MB
__device__ float g_B[CFU * HW];              // sF_fused  [c][pix]   9.4 MB
__device__ float g_G[(size_t)HW * HW];       // Gram [u][v]          67 MB
__device__ float g_P[HW];                    // per-pixel sumsq of B
__device__ float g_invdiv[NK];               // 1/(patch_norm + 1e-7)
__device__ int   g_idx[NK];                  // argmax per query
__device__ float g_stats[2048];              // [0:512) mean cF, [512:1024) invstd cF,
                                             // [1024:1536) mean sF, [1536:2048) invstd sF
__device__ float g_sFt[HW * CH];             // sF transposed [pix][c]

// ---------------- per-channel mean / unbiased-std ----------------
__global__ void stats_kernel(const float* __restrict__ cF,
                             const float* __restrict__ sF) {
    int b = blockIdx.x;          // 0..1023
    int tensor = b >> 9;         // 0 = cF, 1 = sF
    int c = b & 511;
    const float* src = (tensor ? sF : cF) + (size_t)c * HW;

    double s = 0.0, s2 = 0.0;
    for (int i = threadIdx.x; i < HW; i += 256) {
        double v = (double)src[i];
        s += v; s2 += v * v;
    }
    __shared__ double sh[256], sh2[256];
    sh[threadIdx.x] = s; sh2[threadIdx.x] = s2;
    __syncthreads();
    for (int st = 128; st > 0; st >>= 1) {
        if (threadIdx.x < st) {
            sh[threadIdx.x]  += sh[threadIdx.x + st];
            sh2[threadIdx.x] += sh2[threadIdx.x + st];
        }
        __syncthreads();
    }
    if (threadIdx.x == 0) {
        double mean = sh[0] / (double)HW;
        double var  = (sh2[0] - (double)HW * mean * mean) / (double)(HW - 1);
        float sd = sqrtf((float)var + 1e-5f);
        g_stats[tensor * 1024 + c]       = (float)mean;
        g_stats[tensor * 1024 + 512 + c] = 1.0f / sd;
    }
}

// ---------------- build fused tensors A (content) / B (style) ----------------
__global__ void build_kernel(const float* __restrict__ cF,
                             const float* __restrict__ sF,
                             const float* __restrict__ cFs,
                             const float* __restrict__ sFs) {
    int id = blockIdx.x * blockDim.x + threadIdx.x;   // 2 * 576 * 4096
    int t = id / (CFU * HW);
    int r = id - t * (CFU * HW);
    int c = r / HW;
    int u = r - c * HW;
    if (t == 0) {
        float v;
        if (c < CH) v = (cF[c * HW + u] - g_stats[c]) * g_stats[512 + c];
        else        v = 0.5f * cFs[(c - CH) * HW + u];
        g_A[r] = v;
    } else {
        float v;
        if (c < CH) v = (sF[c * HW + u] - g_stats[1024 + c]) * g_stats[1536 + c];
        else        v = 0.5f * sFs[(c - CH) * HW + u];
        g_B[r] = v;
    }
}

// ---------------- per-pixel sum of squares of B ----------------
__global__ void psum_kernel() {
    int v = blockIdx.x * blockDim.x + threadIdx.x;    // 4096
    float s = 0.f;
    for (int c = 0; c < CFU; c++) {
        float x = g_B[c * HW + v];
        s += x * x;
    }
    g_P[v] = s;
}

// ---------------- patch norm reciprocals ----------------
__global__ void invdiv_kernel() {
    int k = blockIdx.x * blockDim.x + threadIdx.x;
    if (k >= NK) return;
    int py = k / HQ, px = k - py * HQ;
    float ns = 0.f;
#pragma unroll
    for (int i = 0; i < 3; i++)
#pragma unroll
        for (int j = 0; j < 3; j++)
            ns += g_P[(py + i) * WID + px + j];
    g_invdiv[k] = 1.0f / (sqrtf(ns) + 1e-7f);
}

// ---------------- Gram GEMM: G = A^T * B (4096x4096x576, fp32) ----------------
__global__ __launch_bounds__(256) void gemm_kernel() {
    __shared__ float As[8][128];
    __shared__ float Bs[8][128];
    const int tid = threadIdx.x;
    const int tx = tid & 15;          // v sub-tile
    const int ty = tid >> 4;          // u sub-tile
    const int u0 = blockIdx.y * 128;
    const int v0 = blockIdx.x * 128;

    float acc[8][8];
#pragma unroll
    for (int i = 0; i < 8; i++)
#pragma unroll
        for (int j = 0; j < 8; j++) acc[i][j] = 0.f;

    const int lk = tid >> 5;          // 0..7   (k row within tile)
    const int lc = (tid & 31) * 4;    // 0..124 (col, float4)

    for (int c0 = 0; c0 < CFU; c0 += 8) {
        float4 a4 = *(const float4*)&g_A[(c0 + lk) * HW + u0 + lc];
        float4 b4 = *(const float4*)&g_B[(c0 + lk) * HW + v0 + lc];
        *(float4*)&As[lk][lc] = a4;
        *(float4*)&Bs[lk][lc] = b4;
        __syncthreads();
#pragma unroll
        for (int kk = 0; kk < 8; kk++) {
            float4 a0 = *(const float4*)&As[kk][ty * 8];
            float4 a1 = *(const float4*)&As[kk][ty * 8 + 4];
            float4 b0 = *(const float4*)&Bs[kk][tx * 8];
            float4 b1 = *(const float4*)&Bs[kk][tx * 8 + 4];
            float ar[8] = {a0.x, a0.y, a0.z, a0.w, a1.x, a1.y, a1.z, a1.w};
            float br[8] = {b0.x, b0.y, b0.z, b0.w, b1.x, b1.y, b1.z, b1.w};
#pragma unroll
            for (int i = 0; i < 8; i++)
#pragma unroll
                for (int j = 0; j < 8; j++)
                    acc[i][j] += ar[i] * br[j];
        }
        __syncthreads();
    }
#pragma unroll
    for (int i = 0; i < 8; i++) {
        int u = u0 + ty * 8 + i;
#pragma unroll
        for (int j = 0; j < 8; j += 4) {
            float4 o = make_float4(acc[i][j], acc[i][j + 1], acc[i][j + 2], acc[i][j + 3]);
            *(float4*)&g_G[(size_t)u * HW + v0 + tx * 8 + j] = o;
        }
    }
}

// ---------------- argmax over keys per query ----------------
__global__ __launch_bounds__(256) void argmax_kernel() {
    int q = blockIdx.x;
    int qy = q / HQ, qx = q - (q / HQ) * HQ;

    const float* base[9];
#pragma unroll
    for (int i = 0; i < 3; i++)
#pragma unroll
        for (int j = 0; j < 3; j++)
            base[i * 3 + j] = g_G + (size_t)((qy + i) * WID + qx + j) * HW + i * WID + j;

    float best = -3.4e38f;
    int bestk = 0x7fffffff;
    for (int k = threadIdx.x; k < NK; k += 256) {
        int py = k / HQ, px = k - py * HQ;
        int col0 = py * WID + px;
        float s = 0.f;
#pragma unroll
        for (int t = 0; t < 9; t++) s += base[t][col0];
        s *= g_invdiv[k];
        if (s > best || (s == best && k < bestk)) { best = s; bestk = k; }
    }

    __shared__ float sv[256];
    __shared__ int   sk[256];
    sv[threadIdx.x] = best; sk[threadIdx.x] = bestk;
    __syncthreads();
    for (int st = 128; st > 0; st >>= 1) {
        if (threadIdx.x < st) {
            float v2 = sv[threadIdx.x + st]; int k2 = sk[threadIdx.x + st];
            if (v2 > sv[threadIdx.x] || (v2 == sv[threadIdx.x] && k2 < sk[threadIdx.x])) {
                sv[threadIdx.x] = v2; sk[threadIdx.x] = k2;
            }
        }
        __syncthreads();
    }
    if (threadIdx.x == 0) g_idx[q] = sk[0];
}

// ---------------- transpose sF -> [pix][c] for coalesced gathers ----------------
__global__ void transpose_kernel(const float* __restrict__ sF) {
    __shared__ float tile[32][33];
    int x = blockIdx.x * 32 + threadIdx.x;       // pixel
    for (int r = threadIdx.y; r < 32; r += 8) {
        int c = blockIdx.y * 32 + r;
        tile[r][threadIdx.x] = sF[c * HW + x];
    }
    __syncthreads();
    int c2 = blockIdx.y * 32 + threadIdx.x;      // channel
    for (int r = threadIdx.y; r < 32; r += 8) {
        int p = blockIdx.x * 32 + r;
        g_sFt[p * CH + c2] = tile[threadIdx.x][r];
    }
}

// ---------------- gather best patches + overlap-add + blend ----------------
__global__ __launch_bounds__(128) void out_kernel(const float* __restrict__ cF,
                                                  float* __restrict__ out) {
    int pix = blockIdx.x;
    int y = pix >> 6, x = pix & 63;
    __shared__ int srcs[9];
    __shared__ int mcount;
    if (threadIdx.x == 0) {
        int m = 0;
        for (int i = 0; i < 3; i++)
            for (int j = 0; j < 3; j++) {
                int qy = y - i, qx = x - j;
                if (qy >= 0 && qy < HQ && qx >= 0 && qx < HQ) {
                    int k = g_idx[qy * HQ + qx];
                    int py = k / HQ, px = k - py * HQ;
                    srcs[m++] = (py + i) * WID + (px + j);
                }
            }
        mcount = m;
    }
    __syncthreads();
    int m = mcount;
    float inv = 1.0f / (float)m;
    for (int c = threadIdx.x; c < CH; c += 128) {
        float acc = 0.f;
        for (int t = 0; t < m; t++) acc += g_sFt[srcs[t] * CH + c];
        out[c * HW + pix] = 0.6f * (acc * inv) + 0.4f * cF[c * HW + pix];
    }
}

// ---------------- launch ----------------
extern "C" void kernel_launch(void* const* d_in, const int* in_sizes, int n_in,
                              void* d_out, int out_size) {
    const float* cF  = (const float*)d_in[0];
    const float* sF  = (const float*)d_in[1];
    const float* cFs = (const float*)d_in[2];
    const float* sFs = (const float*)d_in[3];
    float* out = (float*)d_out;

    stats_kernel<<<1024, 256>>>(cF, sF);
    build_kernel<<<(2 * CFU * HW) / 256, 256>>>(cF, sF, cFs, sFs);
    psum_kernel<<<HW / 256, 256>>>();
    invdiv_kernel<<<(NK + 255) / 256, 256>>>();
    gemm_kernel<<<dim3(32, 32), 256>>>();
    argmax_kernel<<<NK, 256>>>();
    transpose_kernel<<<dim3(128, 16), dim3(32, 8)>>>(sF);
    out_kernel<<<HW, 128>>>(cF, out);
}

// round 14
// speedup vs baseline: 1.1543x; 1.1543x over previous
#include <cuda_runtime.h>
#include <cuda_bf16.h>
#include <cstdint>
#include <math.h>

#define CH   512
#define CS   64
#define CFU  576          // fused channels
#define HW   4096         // 64*64
#define WID  64
#define HQ   62           // 64 - 3 + 1
#define NK   3844         // 62*62

#define M_TILE 128
#define N_TILE 256
#define KC     32
#define NCH    (CFU / KC)   // 18

// ---------------- scratch (static device memory; allowed) ----------------
__device__ float g_B[CFU * HW];              // sF_fused fp32 [c][pix] (for norms)
__device__ float g_G[(size_t)HW * HW];       // Gram [u][v]   67 MB
__device__ float g_P[HW];                    // per-pixel sumsq of B
__device__ float g_invdiv[NK];               // 1/(patch_norm + 1e-7)
__device__ int   g_idx[NK];                  // argmax per query
__device__ float g_stats[2048];
__device__ float g_sFt[HW * CH];             // sF transposed [pix][c]

// bf16 3-limb split operands, [pix][c] (K-contiguous)
__device__ __align__(16) __nv_bfloat16 g_Ah[(size_t)HW * CFU];
__device__ __align__(16) __nv_bfloat16 g_Am[(size_t)HW * CFU];
__device__ __align__(16) __nv_bfloat16 g_Al[(size_t)HW * CFU];
__device__ __align__(16) __nv_bfloat16 g_Bh[(size_t)HW * CFU];
__device__ __align__(16) __nv_bfloat16 g_Bm[(size_t)HW * CFU];
__device__ __align__(16) __nv_bfloat16 g_Bl[(size_t)HW * CFU];

// ---------------- helpers ----------------
__device__ __forceinline__ uint32_t smem_u32(const void* p) {
    uint32_t a;
    asm("{ .reg .u64 t; cvta.to.shared.u64 t, %1; cvt.u32.u64 %0, t; }" : "=r"(a) : "l"(p));
    return a;
}
__device__ __forceinline__ uint32_t sw(uint32_t off) {   // conflict-free ldmatrix, 64B rows
    return off ^ ((off >> 3) & 0x30);
}
__device__ __forceinline__ void cp16(uint32_t saddr, const void* gaddr) {
    asm volatile("cp.async.cg.shared.global [%0], [%1], 16;" :: "r"(saddr), "l"(gaddr));
}
__device__ __forceinline__ void cp_commit() { asm volatile("cp.async.commit_group;"); }
__device__ __forceinline__ void ldsm4(uint32_t r[4], uint32_t addr) {
    asm volatile("ldmatrix.sync.aligned.m8n8.x4.shared.b16 {%0,%1,%2,%3}, [%4];"
                 : "=r"(r[0]), "=r"(r[1]), "=r"(r[2]), "=r"(r[3]) : "r"(addr));
}
__device__ __forceinline__ void mma16816(float c[4], const uint32_t a[4],
                                         uint32_t b0, uint32_t b1) {
    asm volatile(
        "mma.sync.aligned.m16n8k16.row.col.f32.bf16.bf16.f32 "
        "{%0,%1,%2,%3}, {%4,%5,%6,%7}, {%8,%9}, {%0,%1,%2,%3};"
        : "+f"(c[0]), "+f"(c[1]), "+f"(c[2]), "+f"(c[3])
        : "r"(a[0]), "r"(a[1]), "r"(a[2]), "r"(a[3]), "r"(b0), "r"(b1));
}

// ---------------- per-channel mean / unbiased-std ----------------
__global__ void stats_kernel(const float* __restrict__ cF,
                             const float* __restrict__ sF) {
    int b = blockIdx.x;
    int tensor = b >> 9;
    int c = b & 511;
    const float* src = (tensor ? sF : cF) + (size_t)c * HW;
    double s = 0.0, s2 = 0.0;
    for (int i = threadIdx.x; i < HW; i += 256) {
        double v = (double)src[i];
        s += v; s2 += v * v;
    }
    __shared__ double sh[256], sh2[256];
    sh[threadIdx.x] = s; sh2[threadIdx.x] = s2;
    __syncthreads();
    for (int st = 128; st > 0; st >>= 1) {
        if (threadIdx.x < st) {
            sh[threadIdx.x]  += sh[threadIdx.x + st];
            sh2[threadIdx.x] += sh2[threadIdx.x + st];
        }
        __syncthreads();
    }
    if (threadIdx.x == 0) {
        double mean = sh[0] / (double)HW;
        double var  = (sh2[0] - (double)HW * mean * mean) / (double)(HW - 1);
        float sd = sqrtf((float)var + 1e-5f);
        g_stats[tensor * 1024 + c]       = (float)mean;
        g_stats[tensor * 1024 + 512 + c] = 1.0f / sd;
    }
}

// ---------------- build fused tensors, split to 3 bf16 limbs, transpose ------
__global__ void build_kernel(const float* __restrict__ cF,
                             const float* __restrict__ sF,
                             const float* __restrict__ cFs,
                             const float* __restrict__ sFs) {
    __shared__ __nv_bfloat16 sh_h[32][33];
    __shared__ __nv_bfloat16 sh_m[32][33];
    __shared__ __nv_bfloat16 sh_l[32][33];
    const int t = blockIdx.z;
    const int u0 = blockIdx.x * 32;
    const int c0 = blockIdx.y * 32;
    const int u = u0 + threadIdx.x;

    for (int r = threadIdx.y; r < 32; r += 8) {
        int c = c0 + r;
        float v;
        if (t == 0) {
            if (c < CH) v = (cF[c * HW + u] - g_stats[c]) * g_stats[512 + c];
            else        v = 0.5f * cFs[(c - CH) * HW + u];
        } else {
            if (c < CH) v = (sF[c * HW + u] - g_stats[1024 + c]) * g_stats[1536 + c];
            else        v = 0.5f * sFs[(c - CH) * HW + u];
            g_B[c * HW + u] = v;
        }
        __nv_bfloat16 h = __float2bfloat16(v);
        float r1 = v - __bfloat162float(h);
        __nv_bfloat16 m = __float2bfloat16(r1);
        float r2 = r1 - __bfloat162float(m);
        sh_h[r][threadIdx.x] = h;
        sh_m[r][threadIdx.x] = m;
        sh_l[r][threadIdx.x] = __float2bfloat16(r2);
    }
    __syncthreads();
    __nv_bfloat16* Oh = t ? g_Bh : g_Ah;
    __nv_bfloat16* Om = t ? g_Bm : g_Am;
    __nv_bfloat16* Ol = t ? g_Bl : g_Al;
    int c = c0 + threadIdx.x;
    for (int r = threadIdx.y; r < 32; r += 8) {
        size_t u2 = (size_t)(u0 + r);
        Oh[u2 * CFU + c] = sh_h[threadIdx.x][r];
        Om[u2 * CFU + c] = sh_m[threadIdx.x][r];
        Ol[u2 * CFU + c] = sh_l[threadIdx.x][r];
    }
}

// ---------------- per-pixel sum of squares of B ----------------
__global__ void psum_kernel() {
    int v = blockIdx.x * blockDim.x + threadIdx.x;
    float s = 0.f;
    for (int c = 0; c < CFU; c++) {
        float x = g_B[c * HW + v];
        s += x * x;
    }
    g_P[v] = s;
}

// ---------------- patch norm reciprocals ----------------
__global__ void invdiv_kernel() {
    int k = blockIdx.x * blockDim.x + threadIdx.x;
    if (k >= NK) return;
    int py = k / HQ, px = k - py * HQ;
    float ns = 0.f;
#pragma unroll
    for (int i = 0; i < 3; i++)
#pragma unroll
        for (int j = 0; j < 3; j++)
            ns += g_P[(py + i) * WID + px + j];
    g_invdiv[k] = 1.0f / (sqrtf(ns) + 1e-7f);
}

// ---------------- HMMA Gram GEMM: G = A * B^T (3-limb bf16, 6 terms) --------
// stage: Ah 8K | Am 8K | Al 8K | Bh 16K | Bm 16K | Bl 16K = 72K, x2 = 144K
#define O_AH 0
#define O_AM 8192
#define O_AL 16384
#define O_BH 24576
#define O_BM 40960
#define O_BL 57344
#define ST_BYTES 73728

__global__ void __launch_bounds__(256, 1) mma_gemm_kernel() {
    extern __shared__ __align__(1024) char smem[];
    const uint32_t sb = smem_u32(smem);
    const int tid = threadIdx.x;
    const int wid = tid >> 5, lane = tid & 31;
    const int u0 = blockIdx.y * M_TILE;
    const int v0 = blockIdx.x * N_TILE;
    const int m0 = (wid & 1) * 64;          // warp M offset in tile
    const int n0 = (wid >> 1) * 64;         // warp N offset in tile

    const int lrow = lane & 15;
    const uint32_t lkb = ((lane >> 4) & 1) * 16;

    float acc[4][8][4];
#pragma unroll
    for (int i = 0; i < 4; i++)
#pragma unroll
        for (int j = 0; j < 8; j++)
#pragma unroll
            for (int q = 0; q < 4; q++) acc[i][j][q] = 0.f;

    auto load_stage = [&](int ch, int s) {
        const uint32_t base = sb + s * ST_BYTES;
        const int c0 = ch * KC;
        for (int t = tid; t < 512; t += 256) {          // A: 128 rows x 4 segs
            int row = t >> 2, seg = t & 3;
            uint32_t so = sw(row * 64 + seg * 16);
            size_t go = (size_t)(u0 + row) * CFU + c0 + seg * 8;
            cp16(base + O_AH + so, g_Ah + go);
            cp16(base + O_AM + so, g_Am + go);
            cp16(base + O_AL + so, g_Al + go);
        }
        for (int t = tid; t < 1024; t += 256) {         // B: 256 rows x 4 segs
            int row = t >> 2, seg = t & 3;
            uint32_t so = sw(row * 64 + seg * 16);
            size_t go = (size_t)(v0 + row) * CFU + c0 + seg * 8;
            cp16(base + O_BH + so, g_Bh + go);
            cp16(base + O_BM + so, g_Bm + go);
            cp16(base + O_BL + so, g_Bl + go);
        }
        cp_commit();
    };

    load_stage(0, 0);

    for (int ch = 0; ch < NCH; ch++) {
        if (ch + 1 < NCH) {
            load_stage(ch + 1, (ch + 1) & 1);
            asm volatile("cp.async.wait_group 1;");
        } else {
            asm volatile("cp.async.wait_group 0;");
        }
        __syncthreads();

        const uint32_t base = sb + (ch & 1) * ST_BYTES;
#pragma unroll
        for (int ks = 0; ks < KC / 16; ks++) {
            const uint32_t kb = ks * 32 + lkb;
            uint32_t ah[4][4], bh[4][4], t1[4][4], t2[4][4];
            uint32_t aoff[4], boff[4];
#pragma unroll
            for (int mt = 0; mt < 4; mt++)
                aoff[mt] = sw((m0 + mt * 16 + lrow) * 64 + kb);
#pragma unroll
            for (int p = 0; p < 4; p++)
                boff[p] = sw((n0 + p * 16 + lrow) * 64 + kb);

            // Ah, Bh
#pragma unroll
            for (int mt = 0; mt < 4; mt++) ldsm4(ah[mt], base + O_AH + aoff[mt]);
#pragma unroll
            for (int p = 0; p < 4; p++)    ldsm4(bh[p], base + O_BH + boff[p]);
            // hh
#pragma unroll
            for (int mt = 0; mt < 4; mt++)
#pragma unroll
                for (int p = 0; p < 4; p++) {
                    mma16816(acc[mt][2 * p],     ah[mt], bh[p][0], bh[p][2]);
                    mma16816(acc[mt][2 * p + 1], ah[mt], bh[p][1], bh[p][3]);
                }
            // t1 = Bm; hm
#pragma unroll
            for (int p = 0; p < 4; p++) ldsm4(t1[p], base + O_BM + boff[p]);
#pragma unroll
            for (int mt = 0; mt < 4; mt++)
#pragma unroll
                for (int p = 0; p < 4; p++) {
                    mma16816(acc[mt][2 * p],     ah[mt], t1[p][0], t1[p][2]);
                    mma16816(acc[mt][2 * p + 1], ah[mt], t1[p][1], t1[p][3]);
                }
            // t2 = Am; mh + mm
#pragma unroll
            for (int mt = 0; mt < 4; mt++) ldsm4(t2[mt], base + O_AM + aoff[mt]);
#pragma unroll
            for (int mt = 0; mt < 4; mt++)
#pragma unroll
                for (int p = 0; p < 4; p++) {
                    mma16816(acc[mt][2 * p],     t2[mt], bh[p][0], bh[p][2]);
                    mma16816(acc[mt][2 * p + 1], t2[mt], bh[p][1], bh[p][3]);
                    mma16816(acc[mt][2 * p],     t2[mt], t1[p][0], t1[p][2]);
                    mma16816(acc[mt][2 * p + 1], t2[mt], t1[p][1], t1[p][3]);
                }
            // t1 = Bl; hl
#pragma unroll
            for (int p = 0; p < 4; p++) ldsm4(t1[p], base + O_BL + boff[p]);
#pragma unroll
            for (int mt = 0; mt < 4; mt++)
#pragma unroll
                for (int p = 0; p < 4; p++) {
                    mma16816(acc[mt][2 * p],     ah[mt], t1[p][0], t1[p][2]);
                    mma16816(acc[mt][2 * p + 1], ah[mt], t1[p][1], t1[p][3]);
                }
            // t2 = Al; lh
#pragma unroll
            for (int mt = 0; mt < 4; mt++) ldsm4(t2[mt], base + O_AL + aoff[mt]);
#pragma unroll
            for (int mt = 0; mt < 4; mt++)
#pragma unroll
                for (int p = 0; p < 4; p++) {
                    mma16816(acc[mt][2 * p],     t2[mt], bh[p][0], bh[p][2]);
                    mma16816(acc[mt][2 * p + 1], t2[mt], bh[p][1], bh[p][3]);
                }
        }
        __syncthreads();
    }

    // ---- epilogue ----
    const int g = lane >> 2, t4 = lane & 3;
#pragma unroll
    for (int mt = 0; mt < 4; mt++) {
        size_t r0 = (size_t)(u0 + m0 + mt * 16 + g);
        size_t r1 = r0 + 8;
#pragma unroll
        for (int nt = 0; nt < 8; nt++) {
            int col = v0 + n0 + nt * 8 + 2 * t4;
            *(float2*)&g_G[r0 * HW + col] = make_float2(acc[mt][nt][0], acc[mt][nt][1]);
            *(float2*)&g_G[r1 * HW + col] = make_float2(acc[mt][nt][2], acc[mt][nt][3]);
        }
    }
}

// ---------------- argmax over keys per query ----------------
__global__ __launch_bounds__(256) void argmax_kernel() {
    int q = blockIdx.x;
    int qy = q / HQ, qx = q - (q / HQ) * HQ;

    const float* base[9];
#pragma unroll
    for (int i = 0; i < 3; i++)
#pragma unroll
        for (int j = 0; j < 3; j++)
            base[i * 3 + j] = g_G + (size_t)((qy + i) * WID + qx + j) * HW + i * WID + j;

    float best = -3.4e38f;
    int bestk = 0x7fffffff;
    for (int k = threadIdx.x; k < NK; k += 256) {
        int py = k / HQ, px = k - py * HQ;
        int col0 = py * WID + px;
        float s = 0.f;
#pragma unroll
        for (int t = 0; t < 9; t++) s += base[t][col0];
        s *= g_invdiv[k];
        if (s > best || (s == best && k < bestk)) { best = s; bestk = k; }
    }

    __shared__ float sv[256];
    __shared__ int   sk[256];
    sv[threadIdx.x] = best; sk[threadIdx.x] = bestk;
    __syncthreads();
    for (int st = 128; st > 0; st >>= 1) {
        if (threadIdx.x < st) {
            float v2 = sv[threadIdx.x + st]; int k2 = sk[threadIdx.x + st];
            if (v2 > sv[threadIdx.x] || (v2 == sv[threadIdx.x] && k2 < sk[threadIdx.x])) {
                sv[threadIdx.x] = v2; sk[threadIdx.x] = k2;
            }
        }
        __syncthreads();
    }
    if (threadIdx.x == 0) g_idx[q] = sk[0];
}

// ---------------- transpose sF -> [pix][c] ----------------
__global__ void transpose_kernel(const float* __restrict__ sF) {
    __shared__ float tile[32][33];
    int x = blockIdx.x * 32 + threadIdx.x;
    for (int r = threadIdx.y; r < 32; r += 8) {
        int c = blockIdx.y * 32 + r;
        tile[r][threadIdx.x] = sF[c * HW + x];
    }
    __syncthreads();
    int c2 = blockIdx.y * 32 + threadIdx.x;
    for (int r = threadIdx.y; r < 32; r += 8) {
        int p = blockIdx.x * 32 + r;
        g_sFt[p * CH + c2] = tile[threadIdx.x][r];
    }
}

// ---------------- gather best patches + overlap-add + blend ----------------
__global__ __launch_bounds__(128) void out_kernel(const float* __restrict__ cF,
                                                  float* __restrict__ out) {
    int pix = blockIdx.x;
    int y = pix >> 6, x = pix & 63;
    __shared__ int srcs[9];
    __shared__ int mcount;
    if (threadIdx.x == 0) {
        int m = 0;
        for (int i = 0; i < 3; i++)
            for (int j = 0; j < 3; j++) {
                int qy = y - i, qx = x - j;
                if (qy >= 0 && qy < HQ && qx >= 0 && qx < HQ) {
                    int k = g_idx[qy * HQ + qx];
                    int py = k / HQ, px = k - py * HQ;
                    srcs[m++] = (py + i) * WID + (px + j);
                }
            }
        mcount = m;
    }
    __syncthreads();
    int m = mcount;
    float inv = 1.0f / (float)m;
    for (int c = threadIdx.x; c < CH; c += 128) {
        float acc = 0.f;
        for (int t = 0; t < m; t++) acc += g_sFt[srcs[t] * CH + c];
        out[c * HW + pix] = 0.6f * (acc * inv) + 0.4f * cF[c * HW + pix];
    }
}

// ---------------- launch ----------------
extern "C" void kernel_launch(void* const* d_in, const int* in_sizes, int n_in,
                              void* d_out, int out_size) {
    const float* cF  = (const float*)d_in[0];
    const float* sF  = (const float*)d_in[1];
    const float* cFs = (const float*)d_in[2];
    const float* sFs = (const float*)d_in[3];
    float* out = (float*)d_out;

    cudaFuncSetAttribute(mma_gemm_kernel,
                         cudaFuncAttributeMaxDynamicSharedMemorySize, 2 * ST_BYTES);

    stats_kernel<<<1024, 256>>>(cF, sF);
    build_kernel<<<dim3(HW / 32, CFU / 32, 2), dim3(32, 8)>>>(cF, sF, cFs, sFs);
    psum_kernel<<<HW / 256, 256>>>();
    invdiv_kernel<<<(NK + 255) / 256, 256>>>();
    mma_gemm_kernel<<<dim3(HW / N_TILE, HW / M_TILE), 256, 2 * ST_BYTES>>>();
    argmax_kernel<<<NK, 256>>>();
    transpose_kernel<<<dim3(128, 16), dim3(32, 8)>>>(sF);
    out_kernel<<<HW, 128>>>(cF, out);
}

// round 16
// speedup vs baseline: 1.7316x; 1.5001x over previous
#include <cuda_runtime.h>
#include <cuda_bf16.h>
#include <cuda_fp16.h>
#include <cstdint>
#include <math.h>

#define CH   512
#define CS   64
#define CFU  576          // fused channels
#define HW   4096         // 64*64
#define WID  64
#define HQ   62           // 64 - 3 + 1
#define NK   3844         // 62*62

#define M_TILE 128
#define N_TILE 256
#define KC     32
#define NCH    (CFU / KC)   // 18

// ---------------- scratch (static device memory; allowed) ----------------
__device__ float g_B[CFU * HW];              // sF_fused fp32 [c][pix] (for norms)
__device__ float g_G[(size_t)HW * HW];       // Gram [u][v]   67 MB
__device__ float g_P[HW];                    // per-pixel sumsq of B
__device__ float g_invdiv[NK];               // 1/(patch_norm + 1e-7)
__device__ int   g_idx[NK];                  // argmax per query
__device__ float g_stats[2048];
__device__ float g_sFt[HW * CH];             // sF transposed [pix][c]

// fp16 2-limb split operands, [pix][c] (K-contiguous)
__device__ __align__(16) __half g_Ah[(size_t)HW * CFU];
__device__ __align__(16) __half g_Al[(size_t)HW * CFU];
__device__ __align__(16) __half g_Bh[(size_t)HW * CFU];
__device__ __align__(16) __half g_Bl[(size_t)HW * CFU];

// ---------------- helpers ----------------
__device__ __forceinline__ uint32_t smem_u32(const void* p) {
    uint32_t a;
    asm("{ .reg .u64 t; cvta.to.shared.u64 t, %1; cvt.u32.u64 %0, t; }" : "=r"(a) : "l"(p));
    return a;
}
__device__ __forceinline__ uint32_t sw(uint32_t off) {   // conflict-free ldmatrix, 64B rows
    return off ^ ((off >> 3) & 0x30);
}
__device__ __forceinline__ void cp16(uint32_t saddr, const void* gaddr) {
    asm volatile("cp.async.cg.shared.global [%0], [%1], 16;" :: "r"(saddr), "l"(gaddr));
}
__device__ __forceinline__ void cp_commit() { asm volatile("cp.async.commit_group;"); }
__device__ __forceinline__ void ldsm4(uint32_t r[4], uint32_t addr) {
    asm volatile("ldmatrix.sync.aligned.m8n8.x4.shared.b16 {%0,%1,%2,%3}, [%4];"
                 : "=r"(r[0]), "=r"(r[1]), "=r"(r[2]), "=r"(r[3]) : "r"(addr));
}
__device__ __forceinline__ void mma16816(float c[4], const uint32_t a[4],
                                         uint32_t b0, uint32_t b1) {
    asm volatile(
        "mma.sync.aligned.m16n8k16.row.col.f32.f16.f16.f32 "
        "{%0,%1,%2,%3}, {%4,%5,%6,%7}, {%8,%9}, {%0,%1,%2,%3};"
        : "+f"(c[0]), "+f"(c[1]), "+f"(c[2]), "+f"(c[3])
        : "r"(a[0]), "r"(a[1]), "r"(a[2]), "r"(a[3]), "r"(b0), "r"(b1));
}

// ---------------- per-channel mean / unbiased-std ----------------
__global__ void stats_kernel(const float* __restrict__ cF,
                             const float* __restrict__ sF) {
    int b = blockIdx.x;
    int tensor = b >> 9;
    int c = b & 511;
    const float* src = (tensor ? sF : cF) + (size_t)c * HW;
    double s = 0.0, s2 = 0.0;
    for (int i = threadIdx.x; i < HW; i += 256) {
        double v = (double)src[i];
        s += v; s2 += v * v;
    }
    __shared__ double sh[256], sh2[256];
    sh[threadIdx.x] = s; sh2[threadIdx.x] = s2;
    __syncthreads();
    for (int st = 128; st > 0; st >>= 1) {
        if (threadIdx.x < st) {
            sh[threadIdx.x]  += sh[threadIdx.x + st];
            sh2[threadIdx.x] += sh2[threadIdx.x + st];
        }
        __syncthreads();
    }
    if (threadIdx.x == 0) {
        double mean = sh[0] / (double)HW;
        double var  = (sh2[0] - (double)HW * mean * mean) / (double)(HW - 1);
        float sd = sqrtf((float)var + 1e-5f);
        g_stats[tensor * 1024 + c]       = (float)mean;
        g_stats[tensor * 1024 + 512 + c] = 1.0f / sd;
    }
}

// ---------------- build fused tensors, split to 2 fp16 limbs, transpose ------
__global__ void build_kernel(const float* __restrict__ cF,
                             const float* __restrict__ sF,
                             const float* __restrict__ cFs,
                             const float* __restrict__ sFs) {
    __shared__ __half sh_h[32][33];
    __shared__ __half sh_l[32][33];
    const int t = blockIdx.z;
    const int u0 = blockIdx.x * 32;
    const int c0 = blockIdx.y * 32;
    const int u = u0 + threadIdx.x;

    for (int r = threadIdx.y; r < 32; r += 8) {
        int c = c0 + r;
        float v;
        if (t == 0) {
            if (c < CH) v = (cF[c * HW + u] - g_stats[c]) * g_stats[512 + c];
            else        v = 0.5f * cFs[(c - CH) * HW + u];
        } else {
            if (c < CH) v = (sF[c * HW + u] - g_stats[1024 + c]) * g_stats[1536 + c];
            else        v = 0.5f * sFs[(c - CH) * HW + u];
            g_B[c * HW + u] = v;
        }
        __half h = __float2half_rn(v);
        float r1 = v - __half2float(h);
        sh_h[r][threadIdx.x] = h;
        sh_l[r][threadIdx.x] = __float2half_rn(r1);
    }
    __syncthreads();
    __half* Oh = t ? g_Bh : g_Ah;
    __half* Ol = t ? g_Bl : g_Al;
    int c = c0 + threadIdx.x;
    for (int r = threadIdx.y; r < 32; r += 8) {
        size_t u2 = (size_t)(u0 + r);
        Oh[u2 * CFU + c] = sh_h[threadIdx.x][r];
        Ol[u2 * CFU + c] = sh_l[threadIdx.x][r];
    }
}

// ---------------- per-pixel sum of squares of B ----------------
__global__ void psum_kernel() {
    int v = blockIdx.x * blockDim.x + threadIdx.x;
    float s = 0.f;
    for (int c = 0; c < CFU; c++) {
        float x = g_B[c * HW + v];
        s += x * x;
    }
    g_P[v] = s;
}

// ---------------- patch norm reciprocals ----------------
__global__ void invdiv_kernel() {
    int k = blockIdx.x * blockDim.x + threadIdx.x;
    if (k >= NK) return;
    int py = k / HQ, px = k - py * HQ;
    float ns = 0.f;
#pragma unroll
    for (int i = 0; i < 3; i++)
#pragma unroll
        for (int j = 0; j < 3; j++)
            ns += g_P[(py + i) * WID + px + j];
    g_invdiv[k] = 1.0f / (sqrtf(ns) + 1e-7f);
}

// ---------------- HMMA Gram GEMM: G = A * B^T (2-limb fp16, 3 terms) --------
// stage: Ah 8K | Al 8K | Bh 16K | Bl 16K = 48K, x3 stages = 144K
#define O_AH 0
#define O_AL 8192
#define O_BH 16384
#define O_BL 32768
#define ST_BYTES 49152
#define N_STAGE 3

__global__ void __launch_bounds__(256, 1) mma_gemm_kernel() {
    extern __shared__ __align__(1024) char smem[];
    const uint32_t sb = smem_u32(smem);
    const int tid = threadIdx.x;
    const int wid = tid >> 5, lane = tid & 31;
    const int u0 = blockIdx.y * M_TILE;
    const int v0 = blockIdx.x * N_TILE;
    const int m0 = (wid & 1) * 64;          // warp M offset in tile
    const int n0 = (wid >> 1) * 64;         // warp N offset in tile

    const int lrow = lane & 15;
    const uint32_t lkb = ((lane >> 4) & 1) * 16;

    float acc[4][8][4];
#pragma unroll
    for (int i = 0; i < 4; i++)
#pragma unroll
        for (int j = 0; j < 8; j++)
#pragma unroll
            for (int q = 0; q < 4; q++) acc[i][j][q] = 0.f;

    auto load_stage = [&](int ch) {
        const uint32_t base = sb + (ch % N_STAGE) * ST_BYTES;
        const int c0 = ch * KC;
        for (int t = tid; t < 512; t += 256) {          // A: 128 rows x 4 segs
            int row = t >> 2, seg = t & 3;
            uint32_t so = sw(row * 64 + seg * 16);
            size_t go = (size_t)(u0 + row) * CFU + c0 + seg * 8;
            cp16(base + O_AH + so, g_Ah + go);
            cp16(base + O_AL + so, g_Al + go);
        }
        for (int t = tid; t < 1024; t += 256) {         // B: 256 rows x 4 segs
            int row = t >> 2, seg = t & 3;
            uint32_t so = sw(row * 64 + seg * 16);
            size_t go = (size_t)(v0 + row) * CFU + c0 + seg * 8;
            cp16(base + O_BH + so, g_Bh + go);
            cp16(base + O_BL + so, g_Bl + go);
        }
        cp_commit();
    };

    load_stage(0);
    load_stage(1);

    for (int ch = 0; ch < NCH; ch++) {
        if (ch + 1 < NCH) asm volatile("cp.async.wait_group 1;");
        else              asm volatile("cp.async.wait_group 0;");
        __syncthreads();
        if (ch + 2 < NCH) load_stage(ch + 2);

        const uint32_t base = sb + (ch % N_STAGE) * ST_BYTES;
#pragma unroll
        for (int ks = 0; ks < KC / 16; ks++) {
            const uint32_t kb = ks * 32 + lkb;
            uint32_t ah[4][4], bh[4][4], xx[4][4];
            uint32_t aoff[4], boff[4];
#pragma unroll
            for (int mt = 0; mt < 4; mt++)
                aoff[mt] = sw((m0 + mt * 16 + lrow) * 64 + kb);
#pragma unroll
            for (int p = 0; p < 4; p++)
                boff[p] = sw((n0 + p * 16 + lrow) * 64 + kb);

            // Ah, Bh fragments
#pragma unroll
            for (int mt = 0; mt < 4; mt++) ldsm4(ah[mt], base + O_AH + aoff[mt]);
#pragma unroll
            for (int p = 0; p < 4; p++)    ldsm4(bh[p], base + O_BH + boff[p]);
            // pass hh
#pragma unroll
            for (int mt = 0; mt < 4; mt++)
#pragma unroll
                for (int p = 0; p < 4; p++) {
                    mma16816(acc[mt][2 * p],     ah[mt], bh[p][0], bh[p][2]);
                    mma16816(acc[mt][2 * p + 1], ah[mt], bh[p][1], bh[p][3]);
                }
            // pass hl: Ah x Bl
#pragma unroll
            for (int p = 0; p < 4; p++) ldsm4(xx[p], base + O_BL + boff[p]);
#pragma unroll
            for (int mt = 0; mt < 4; mt++)
#pragma unroll
                for (int p = 0; p < 4; p++) {
                    mma16816(acc[mt][2 * p],     ah[mt], xx[p][0], xx[p][2]);
                    mma16816(acc[mt][2 * p + 1], ah[mt], xx[p][1], xx[p][3]);
                }
            // pass lh: Al x Bh
#pragma unroll
            for (int mt = 0; mt < 4; mt++) ldsm4(xx[mt], base + O_AL + aoff[mt]);
#pragma unroll
            for (int mt = 0; mt < 4; mt++)
#pragma unroll
                for (int p = 0; p < 4; p++) {
                    mma16816(acc[mt][2 * p],     xx[mt], bh[p][0], bh[p][2]);
                    mma16816(acc[mt][2 * p + 1], xx[mt], bh[p][1], bh[p][3]);
                }
        }
    }

    // ---- epilogue ----
    const int g = lane >> 2, t4 = lane & 3;
#pragma unroll
    for (int mt = 0; mt < 4; mt++) {
        size_t r0 = (size_t)(u0 + m0 + mt * 16 + g);
        size_t r1 = r0 + 8;
#pragma unroll
        for (int nt = 0; nt < 8; nt++) {
            int col = v0 + n0 + nt * 8 + 2 * t4;
            *(float2*)&g_G[r0 * HW + col] = make_float2(acc[mt][nt][0], acc[mt][nt][1]);
            *(float2*)&g_G[r1 * HW + col] = make_float2(acc[mt][nt][2], acc[mt][nt][3]);
        }
    }
}

// ---------------- argmax over keys per query ----------------
__global__ __launch_bounds__(256) void argmax_kernel() {
    int q = blockIdx.x;
    int qy = q / HQ, qx = q - (q / HQ) * HQ;

    const float* base[9];
#pragma unroll
    for (int i = 0; i < 3; i++)
#pragma unroll
        for (int j = 0; j < 3; j++)
            base[i * 3 + j] = g_G + (size_t)((qy + i) * WID + qx + j) * HW + i * WID + j;

    float best = -3.4e38f;
    int bestk = 0x7fffffff;
    for (int k = threadIdx.x; k < NK; k += 256) {
        int py = k / HQ, px = k - py * HQ;
        int col0 = py * WID + px;
        float s = 0.f;
#pragma unroll
        for (int t = 0; t < 9; t++) s += base[t][col0];
        s *= g_invdiv[k];
        if (s > best || (s == best && k < bestk)) { best = s; bestk = k; }
    }

    __shared__ float sv[256];
    __shared__ int   sk[256];
    sv[threadIdx.x] = best; sk[threadIdx.x] = bestk;
    __syncthreads();
    for (int st = 128; st > 0; st >>= 1) {
        if (threadIdx.x < st) {
            float v2 = sv[threadIdx.x + st]; int k2 = sk[threadIdx.x + st];
            if (v2 > sv[threadIdx.x] || (v2 == sv[threadIdx.x] && k2 < sk[threadIdx.x])) {
                sv[threadIdx.x] = v2; sk[threadIdx.x] = k2;
            }
        }
        __syncthreads();
    }
    if (threadIdx.x == 0) g_idx[q] = sk[0];
}

// ---------------- transpose sF -> [pix][c] ----------------
__global__ void transpose_kernel(const float* __restrict__ sF) {
    __shared__ float tile[32][33];
    int x = blockIdx.x * 32 + threadIdx.x;
    for (int r = threadIdx.y; r < 32; r += 8) {
        int c = blockIdx.y * 32 + r;
        tile[r][threadIdx.x] = sF[c * HW + x];
    }
    __syncthreads();
    int c2 = blockIdx.y * 32 + threadIdx.x;
    for (int r = threadIdx.y; r < 32; r += 8) {
        int p = blockIdx.x * 32 + r;
        g_sFt[p * CH + c2] = tile[threadIdx.x][r];
    }
}

// ---------------- gather best patches + overlap-add + blend ----------------
__global__ __launch_bounds__(128) void out_kernel(const float* __restrict__ cF,
                                                  float* __restrict__ out) {
    int pix = blockIdx.x;
    int y = pix >> 6, x = pix & 63;
    __shared__ int srcs[9];
    __shared__ int mcount;
    if (threadIdx.x == 0) {
        int m = 0;
        for (int i = 0; i < 3; i++)
            for (int j = 0; j < 3; j++) {
                int qy = y - i, qx = x - j;
                if (qy >= 0 && qy < HQ && qx >= 0 && qx < HQ) {
                    int k = g_idx[qy * HQ + qx];
                    int py = k / HQ, px = k - py * HQ;
                    srcs[m++] = (py + i) * WID + (px + j);
                }
            }
        mcount = m;
    }
    __syncthreads();
    int m = mcount;
    float inv = 1.0f / (float)m;
    for (int c = threadIdx.x; c < CH; c += 128) {
        float acc = 0.f;
        for (int t = 0; t < m; t++) acc += g_sFt[srcs[t] * CH + c];
        out[c * HW + pix] = 0.6f * (acc * inv) + 0.4f * cF[c * HW + pix];
    }
}

// ---------------- launch ----------------
extern "C" void kernel_launch(void* const* d_in, const int* in_sizes, int n_in,
                              void* d_out, int out_size) {
    const float* cF  = (const float*)d_in[0];
    const float* sF  = (const float*)d_in[1];
    const float* cFs = (const float*)d_in[2];
    const float* sFs = (const float*)d_in[3];
    float* out = (float*)d_out;

    cudaFuncSetAttribute(mma_gemm_kernel,
                         cudaFuncAttributeMaxDynamicSharedMemorySize, N_STAGE * ST_BYTES);

    stats_kernel<<<1024, 256>>>(cF, sF);
    build_kernel<<<dim3(HW / 32, CFU / 32, 2), dim3(32, 8)>>>(cF, sF, cFs, sFs);
    psum_kernel<<<HW / 256, 256>>>();
    invdiv_kernel<<<(NK + 255) / 256, 256>>>();
    mma_gemm_kernel<<<dim3(HW / N_TILE, HW / M_TILE), 256, N_STAGE * ST_BYTES>>>();
    argmax_kernel<<<NK, 256>>>();
    transpose_kernel<<<dim3(128, 16), dim3(32, 8)>>>(sF);
    out_kernel<<<HW, 128>>>(cF, out);
}